// round 14
// baseline (speedup 1.0000x reference)
#include <cuda_runtime.h>
#include <cstdint>
#include <math.h>

#define BB 32
#define TT 256
#define DD 512
#define HH 2048
#define VV 32000
#define BT (BB*TT)          // 8192
#define NBN 125             // vgemm N panels

// ---------------- scratch (device globals; no allocation allowed) ------------
__device__ float g_ux[BT*HH];            // [T][B][H] input projection
__device__ float g_hr[BT*HH];            // [B,T,H] tf32 h, K-permuted in 16-blk
__device__ float g_hT[2][HH*BB];         // transposed h double buffer [k][b]
__device__ float g_wP[(size_t)HH*HH];    // W packed: [blk][k][16 cols]
__device__ float g_vw[(size_t)VV*HH];    // tf32 V_w, K-permuted in 16-blk
__device__ float g_part2[(size_t)NBN*BT];// exp-sum partials [bn][row]
__device__ float g_rowloss[BT];

// ---------------- f32x2 packed helpers --------------------------------------
__device__ __forceinline__ unsigned long long pk2(float a, float b) {
    unsigned long long r;
    asm("mov.b64 %0, {%1, %2};" : "=l"(r) : "f"(a), "f"(b));
    return r;
}
__device__ __forceinline__ void fma2(unsigned long long& acc,
                                     unsigned long long a, unsigned long long b) {
    asm("fma.rn.f32x2 %0, %1, %2, %0;" : "+l"(acc) : "l"(a), "l"(b));
}
__device__ __forceinline__ void unpk2(unsigned long long v, float& lo, float& hi) {
    asm("mov.b64 {%0, %1}, %2;" : "=f"(lo), "=f"(hi) : "l"(v));
}

// ======================= Kernel A: ux = C[xb] @ U^T + b ======================
// M=8192, N=2048, K=512. 128x128 tile, BK=16, 256 thr, 8x8/thread.
// Inner loop on packed FFMA2 (f32x2): 32 fma2 + 4 LDS per k vs 64 FFMA + 4 LDS.
__global__ __launch_bounds__(256) void k_uproj(const int* __restrict__ xb,
                                               const float* __restrict__ Cemb,
                                               const float* __restrict__ Uw,
                                               const float* __restrict__ Ub)
{
    __shared__ float As[16][128];
    __shared__ float Bs[16][128];
    const int bn = blockIdx.x, bm = blockIdx.y;
    const int tid = threadIdx.x;
    const int tx = tid & 15, ty = tid >> 4;

    unsigned long long acc2[8][4];
    #pragma unroll
    for (int i = 0; i < 8; ++i)
        #pragma unroll
        for (int j = 0; j < 4; ++j) acc2[i][j] = 0ull;

    for (int c = 0; c < DD/16; ++c) {
        const int k0 = c * 16;
        #pragma unroll
        for (int it = 0; it < 2; ++it) {
            int idx = tid + it*256;
            int r = idx & 127, q = idx >> 7;
            int tok = xb[bm*128 + r];
            float4 v = *(const float4*)&Cemb[(size_t)tok*DD + k0 + q*4];
            As[q*4+0][r] = v.x; As[q*4+1][r] = v.y;
            As[q*4+2][r] = v.z; As[q*4+3][r] = v.w;
        }
        #pragma unroll
        for (int it = 0; it < 2; ++it) {
            int idx = tid + it*256;
            int r = idx & 127, q = idx >> 7;
            float4 v = *(const float4*)&Uw[(size_t)(bn*128 + r)*DD + k0 + q*4];
            Bs[q*4+0][r] = v.x; Bs[q*4+1][r] = v.y;
            Bs[q*4+2][r] = v.z; Bs[q*4+3][r] = v.w;
        }
        __syncthreads();
        #pragma unroll
        for (int k = 0; k < 16; ++k) {
            float a[8];
            *(float4*)(a)   = *(float4*)&As[k][ty*8];
            *(float4*)(a+4) = *(float4*)&As[k][ty*8+4];
            unsigned long long bp0, bp1, bp2, bp3;
            unsigned baddr = (unsigned)__cvta_generic_to_shared(&Bs[k][tx*8]);
            asm("ld.shared.v2.u64 {%0,%1}, [%2];" : "=l"(bp0), "=l"(bp1) : "r"(baddr));
            asm("ld.shared.v2.u64 {%0,%1}, [%2];" : "=l"(bp2), "=l"(bp3) : "r"(baddr+16));
            #pragma unroll
            for (int i = 0; i < 8; ++i) {
                unsigned long long ap = pk2(a[i], a[i]);
                fma2(acc2[i][0], bp0, ap);
                fma2(acc2[i][1], bp1, ap);
                fma2(acc2[i][2], bp2, ap);
                fma2(acc2[i][3], bp3, ap);
            }
        }
        __syncthreads();
    }
    const int n0 = bn*128 + tx*8;
    float ub[8];
    #pragma unroll
    for (int j = 0; j < 8; ++j) ub[j] = Ub[n0+j];
    #pragma unroll
    for (int i = 0; i < 8; ++i) {
        int m = bm*128 + ty*8 + i;       // m = b*TT + t
        int t = m & 255, b = m >> 8;
        size_t dst = ((size_t)t*BB + b)*HH + n0;
        float r[8];
        unpk2(acc2[i][0], r[0], r[1]); unpk2(acc2[i][1], r[2], r[3]);
        unpk2(acc2[i][2], r[4], r[5]); unpk2(acc2[i][3], r[6], r[7]);
        float4 o0 = {r[0]+ub[0], r[1]+ub[1], r[2]+ub[2], r[3]+ub[3]};
        float4 o1 = {r[4]+ub[4], r[5]+ub[5], r[6]+ub[6], r[7]+ub[7]};
        *(float4*)&g_ux[dst]     = o0;
        *(float4*)&g_ux[dst + 4] = o1;
    }
}

// ============ pack W for the recurrence: g_wP[blk][k][c16] = W[blk*16+c][k] ==
__global__ __launch_bounds__(512) void k_packW(const float* __restrict__ Ww)
{
    __shared__ float tile[32][17];
    const int bx = blockIdx.x;           // k-tile (0..63)
    const int by = blockIdx.y;           // col-block (0..127)
    const int tid = threadIdx.x;
    {
        int c = tid >> 5, kk = tid & 31;
        tile[kk][c] = Ww[(size_t)(by*16 + c)*HH + bx*32 + kk];
    }
    __syncthreads();
    {
        int kk = tid >> 4, c = tid & 15;
        g_wP[(size_t)by*(HH*16) + (size_t)(bx*32 + kk)*16 + c] = tile[kk][c];
    }
}

// ===== pre-round V_w to tf32, store K-permuted within 16-blocks ==============
__global__ __launch_bounds__(256) void k_round_vw(const float* __restrict__ Vw)
{
    size_t i = ((size_t)blockIdx.x*256 + threadIdx.x) * 4;
    float4 v = *(const float4*)&Vw[i];
    float4 o;
    asm("cvt.rna.tf32.f32 %0, %1;" : "=f"(o.x) : "f"(v.x));
    asm("cvt.rna.tf32.f32 %0, %1;" : "=f"(o.y) : "f"(v.y));
    asm("cvt.rna.tf32.f32 %0, %1;" : "=f"(o.z) : "f"(v.z));
    asm("cvt.rna.tf32.f32 %0, %1;" : "=f"(o.w) : "f"(v.w));
    size_t base16 = i & ~(size_t)15;
    size_t q = (i >> 2) & 3;
    g_vw[base16 + q + 0]  = o.x;
    g_vw[base16 + q + 4]  = o.y;
    g_vw[base16 + q + 8]  = o.z;
    g_vw[base16 + q + 12] = o.w;
}

// ============== prologue: h0 fill (graph-replay safe) ========================
__global__ __launch_bounds__(256) void k_rnn_init()
{
    int i = blockIdx.x*256 + threadIdx.x;
    g_hT[0][i] = 0.1f;
}

// ================= one Elman timestep: h_t = tanh(ux_t + W h_{t-1}) ==========
__global__ __launch_bounds__(256, 1) void k_step(int t)
{
    extern __shared__ float sm[];
    float* hs   = sm;            // 2 x [256 k][32 b] = 16384 floats (64 KB)
    float* ws   = sm + 16384;    // 2 x [256 k][16 c] =  8192 floats (32 KB)
    float* part = sm + 24576;    // [8][512]          =  4096 floats (16 KB)

    const int tid = threadIdx.x;
    const int c2 = tid & 7;
    const int rg = (tid >> 3) & 3;
    const int ks = tid >> 5;                 // warp index = k-slice
    const int cb = blockIdx.x * 16;

    const float4* hsrc = (const float4*)&g_hT[t & 1][0];   // 16384 float4
    const float4* wsrc = (const float4*)(g_wP + (size_t)blockIdx.x*(HH*16));

    auto stage = [&](int c, int s) {
        float* hd = hs + s*8192;
        #pragma unroll
        for (int i = 0; i < 8; ++i) {
            int idx = tid + i*256;
            unsigned d = (unsigned)__cvta_generic_to_shared(hd + idx*4);
            asm volatile("cp.async.cg.shared.global [%0], [%1], 16;\n"
                         :: "r"(d), "l"(hsrc + c*2048 + idx));
        }
        float* wd = ws + s*4096;
        #pragma unroll
        for (int i = 0; i < 4; ++i) {
            int idx = tid + i*256;
            unsigned d = (unsigned)__cvta_generic_to_shared(wd + idx*4);
            asm volatile("cp.async.cg.shared.global [%0], [%1], 16;\n"
                         :: "r"(d), "l"(wsrc + c*1024 + idx));
        }
        asm volatile("cp.async.commit_group;\n");
    };

    stage(0, 0);

    unsigned long long a00=0, a01=0, a02=0, a03=0;
    unsigned long long a10=0, a11=0, a12=0, a13=0;

    for (int ch = 0; ch < 8; ++ch) {
        if (ch < 7) {
            stage(ch + 1, (ch + 1) & 1);
            asm volatile("cp.async.wait_group 1;\n");
        } else {
            asm volatile("cp.async.wait_group 0;\n");
        }
        __syncthreads();

        unsigned hba = (unsigned)__cvta_generic_to_shared(
            hs + (ch & 1)*8192 + (ks*32)*32 + rg*8);
        unsigned wba = (unsigned)__cvta_generic_to_shared(
            ws + (ch & 1)*4096 + (ks*32)*16 + c2*2);

        #pragma unroll 8
        for (int kl = 0; kl < 32; ++kl) {
            float wx, wy;
            asm("ld.shared.v2.f32 {%0, %1}, [%2];" : "=f"(wx), "=f"(wy) : "r"(wba));
            wba += 64;
            unsigned long long w0 = pk2(wx, wx);
            unsigned long long w1 = pk2(wy, wy);
            unsigned long long h01, h23, h45, h67;
            asm("ld.shared.v2.u64 {%0,%1}, [%2];"
                : "=l"(h01), "=l"(h23) : "r"(hba));
            asm("ld.shared.v2.u64 {%0,%1}, [%2];"
                : "=l"(h45), "=l"(h67) : "r"(hba + 16));
            hba += 128;
            fma2(a00, h01, w0); fma2(a01, h23, w0);
            fma2(a02, h45, w0); fma2(a03, h67, w0);
            fma2(a10, h01, w1); fma2(a11, h23, w1);
            fma2(a12, h45, w1); fma2(a13, h67, w1);
        }
        __syncthreads();
    }

    {
        float lo, hi;
        float* p0 = &part[ks*512 + (c2*2 + 0)*32 + rg*8];
        float* p1 = &part[ks*512 + (c2*2 + 1)*32 + rg*8];
        unpk2(a00, lo, hi); p0[0] = lo; p0[1] = hi;
        unpk2(a01, lo, hi); p0[2] = lo; p0[3] = hi;
        unpk2(a02, lo, hi); p0[4] = lo; p0[5] = hi;
        unpk2(a03, lo, hi); p0[6] = lo; p0[7] = hi;
        unpk2(a10, lo, hi); p1[0] = lo; p1[1] = hi;
        unpk2(a11, lo, hi); p1[2] = lo; p1[3] = hi;
        unpk2(a12, lo, hi); p1[4] = lo; p1[5] = hi;
        unpk2(a13, lo, hi); p1[6] = lo; p1[7] = hi;
    }
    __syncthreads();

    #pragma unroll
    for (int u = 0; u < 2; ++u) {
        int o = tid*2 + u;
        int c = o >> 5, b = o & 31;
        float s = part[o] + part[512 + o] + part[1024 + o] + part[1536 + o]
                + part[2048 + o] + part[2560 + o] + part[3072 + o] + part[3584 + o];
        s += g_ux[((size_t)t*BB + b)*HH + cb + c];
        float h = tanhf(s);
        g_hT[(t+1) & 1][(size_t)(cb + c)*BB + b] = h;
        float hr; asm("cvt.rna.tf32.f32 %0, %1;" : "=f"(hr) : "f"(h));
        int permc = ((c & 3) << 2) | (c >> 2);
        g_hr[((size_t)b*TT + t)*HH + cb + permc] = hr;
    }
}

// ---- f16x2 exp helper: returns exp2(y0) + exp2(y1) ---------------------------
__device__ __forceinline__ float exp2pair(float y0, float y1) {
    uint32_t h, e;
    asm("cvt.rn.f16x2.f32 %0, %1, %2;" : "=r"(h) : "f"(y1), "f"(y0));
    asm("ex2.approx.f16x2 %0, %1;" : "=r"(e) : "r"(h));
    float a, b;
    asm("{.reg .f16 l,hh; mov.b32 {l,hh}, %2; cvt.f32.f16 %0, l; cvt.f32.f16 %1, hh;}"
        : "=f"(a), "=f"(b) : "r"(e));
    return a + b;
}

// ================= Kernel C: logits = h @ V_w^T + V_b  (tf32 MMA) ============
// Fused epilogue also produces per-(bn,row) exp-sum partials (shifted by 2^-8)
// into g_part2 — deterministic (no atomics), kills the rowloss logits re-read.
#define VSTAGE 12288    // floats per stage: A 128x32 (4096) + B 256x32 (8192)
__global__ __launch_bounds__(256, 1) void k_vgemm(const float* __restrict__ Vb,
                                                  float* __restrict__ out)
{
    extern __shared__ float smv[];
    __shared__ float s_es[4][128];              // [wn][local row] exp partials

    const int bid = blockIdx.x;                 // 8000 = 8 grp x (8 bm x 125 bn)
    const int grp = bid / 1000;
    const int rem = bid % 1000;
    const int bm  = grp*8 + (rem & 7);          // 0..63
    const int bn  = rem >> 3;                   // 0..124

    const int tid = threadIdx.x;
    const int lane = tid & 31, wid = tid >> 5;
    const int wm = (wid >> 2) * 64, wn = (wid & 3) * 64;
    const int gr = lane >> 2, tg = lane & 3;

    const float* Ag = g_hr + (size_t)(bm*128)*HH;
    const float* Bg = g_vw + (size_t)(bn*256)*HH;

    float acc[4][8][4];
    #pragma unroll
    for (int m = 0; m < 4; ++m)
        #pragma unroll
        for (int n = 0; n < 8; ++n)
            #pragma unroll
            for (int q = 0; q < 4; ++q) acc[m][n][q] = 0.f;

    auto stage_load = [&](int c, int s) {
        float* As = smv + s*VSTAGE;
        float* Bs = As + 4096;
        #pragma unroll
        for (int i = 0; i < 4; ++i) {
            int o = tid + i*256;
            int kg = o >> 9, row = (o >> 2) & 127, q = o & 3;
            unsigned d = (unsigned)__cvta_generic_to_shared(As + o*4);
            const float* src = Ag + (size_t)row*HH + c*32 + kg*16 + q*4;
            asm volatile("cp.async.cg.shared.global [%0], [%1], 16;\n"
                         :: "r"(d), "l"(src));
        }
        #pragma unroll
        for (int i = 0; i < 8; ++i) {
            int o = tid + i*256;
            int kg = o >> 10, row = (o >> 2) & 255, q = o & 3;
            unsigned d = (unsigned)__cvta_generic_to_shared(Bs + o*4);
            const float* src = Bg + (size_t)row*HH + c*32 + kg*16 + q*4;
            asm volatile("cp.async.cg.shared.global [%0], [%1], 16;\n"
                         :: "r"(d), "l"(src));
        }
        asm volatile("cp.async.commit_group;\n");
    };

    stage_load(0, 0);
    stage_load(1, 1);

    int sc = 0, sl = 2;
    const int NCH = HH/32;                        // 64 chunks
    for (int c = 0; c < NCH; ++c) {
        if (c < NCH-1) asm volatile("cp.async.wait_group 1;\n");
        else           asm volatile("cp.async.wait_group 0;\n");
        __syncthreads();
        if (c + 2 < NCH) {
            stage_load(c + 2, sl);
            sl = (sl == 2) ? 0 : sl + 1;
        }

        const float* As = smv + sc*VSTAGE;
        const float* Bs = As + 4096;
        #pragma unroll
        for (int kg = 0; kg < 2; ++kg) {
            float4 af[4][2]; float4 bf[8];
            #pragma unroll
            for (int mt = 0; mt < 4; ++mt) {
                af[mt][0] = *(const float4*)&As[(kg*128 + wm + mt*16 + gr)*16 + tg*4];
                af[mt][1] = *(const float4*)&As[(kg*128 + wm + mt*16 + 8 + gr)*16 + tg*4];
            }
            #pragma unroll
            for (int nt = 0; nt < 8; ++nt)
                bf[nt] = *(const float4*)&Bs[(kg*256 + wn + nt*8 + gr)*16 + tg*4];

            #pragma unroll
            for (int mt = 0; mt < 4; ++mt)
                #pragma unroll
                for (int nt = 0; nt < 8; ++nt) {
                    asm volatile(
                        "mma.sync.aligned.m16n8k8.row.col.f32.tf32.tf32.f32 "
                        "{%0,%1,%2,%3},{%4,%5,%6,%7},{%8,%9},{%0,%1,%2,%3};\n"
                        : "+f"(acc[mt][nt][0]), "+f"(acc[mt][nt][1]),
                          "+f"(acc[mt][nt][2]), "+f"(acc[mt][nt][3])
                        : "r"(__float_as_uint(af[mt][0].x)), "r"(__float_as_uint(af[mt][1].x)),
                          "r"(__float_as_uint(af[mt][0].y)), "r"(__float_as_uint(af[mt][1].y)),
                          "r"(__float_as_uint(bf[nt].x)),    "r"(__float_as_uint(bf[nt].y)));
                    asm volatile(
                        "mma.sync.aligned.m16n8k8.row.col.f32.tf32.tf32.f32 "
                        "{%0,%1,%2,%3},{%4,%5,%6,%7},{%8,%9},{%0,%1,%2,%3};\n"
                        : "+f"(acc[mt][nt][0]), "+f"(acc[mt][nt][1]),
                          "+f"(acc[mt][nt][2]), "+f"(acc[mt][nt][3])
                        : "r"(__float_as_uint(af[mt][0].z)), "r"(__float_as_uint(af[mt][1].z)),
                          "r"(__float_as_uint(af[mt][0].w)), "r"(__float_as_uint(af[mt][1].w)),
                          "r"(__float_as_uint(bf[nt].z)),    "r"(__float_as_uint(bf[nt].w)));
                }
        }
        sc = (sc == 2) ? 0 : sc + 1;
    }

    // epilogue: +bias, store logits, and accumulate exp partials per row
    const float CE = 1.4426950408889634f;   // log2(e)
    #pragma unroll
    for (int mt = 0; mt < 4; ++mt) {
        size_t r0 = (size_t)(bm*128 + wm + mt*16 + gr);
        float sA = 0.f, sB = 0.f;
        #pragma unroll
        for (int nt = 0; nt < 8; ++nt) {
            int col = bn*256 + wn + nt*8 + tg*2;
            float b0 = Vb[col], b1 = Vb[col+1];
            float2 v0 = {acc[mt][nt][0] + b0, acc[mt][nt][1] + b1};
            float2 v1 = {acc[mt][nt][2] + b0, acc[mt][nt][3] + b1};
            *(float2*)&out[r0*VV + col]       = v0;
            *(float2*)&out[(r0+8)*VV + col]   = v1;
            sA += exp2pair(fmaf(v0.x, CE, -8.f), fmaf(v0.y, CE, -8.f));
            sB += exp2pair(fmaf(v1.x, CE, -8.f), fmaf(v1.y, CE, -8.f));
        }
        // quad reduce across tg (4 lanes hold different cols of same row)
        sA += __shfl_xor_sync(0xffffffffu, sA, 1);
        sA += __shfl_xor_sync(0xffffffffu, sA, 2);
        sB += __shfl_xor_sync(0xffffffffu, sB, 1);
        sB += __shfl_xor_sync(0xffffffffu, sB, 2);
        if (tg == 0) {
            s_es[wid & 3][wm + mt*16 + gr]     = sA;
            s_es[wid & 3][wm + mt*16 + 8 + gr] = sB;
        }
    }
    __syncthreads();
    // threads 0..127: combine the 4 wn-warps, store deterministic partial
    if (tid < 128) {
        float s = s_es[0][tid] + s_es[1][tid] + s_es[2][tid] + s_es[3][tid];
        g_part2[(size_t)bn*BT + bm*128 + tid] = s;
    }
}

// ====== Kernel D1: finalize rows: lse from partials, minus target logit ======
__global__ __launch_bounds__(256) void k_rowfinish(const float* __restrict__ logits,
                                                   const int* __restrict__ targets)
{
    int r = blockIdx.x*256 + threadIdx.x;     // grid 32 -> 8192 rows
    float s = 0.f;
    #pragma unroll 5
    for (int j = 0; j < NBN; ++j) s += g_part2[(size_t)j*BT + r];
    float lse = (__log2f(s) + 8.f) * 0.6931471805599453f;
    g_rowloss[r] = lse - logits[(size_t)r*VV + targets[r]];
}

// ================= Kernel D2: mean of row losses -> d_out[last] ==============
__global__ __launch_bounds__(256) void k_loss(float* __restrict__ out, int out_size)
{
    __shared__ float red[256];
    const int tid = threadIdx.x;
    float s = 0.f;
    for (int i = tid; i < BT; i += 256) s += g_rowloss[i];
    red[tid] = s; __syncthreads();
    for (int st = 128; st > 0; st >>= 1) {
        if (tid < st) red[tid] += red[tid+st];
        __syncthreads();
    }
    if (tid == 0) out[(size_t)out_size - 1] = red[0] / (float)BT;
}

// ============================== launch =======================================
extern "C" void kernel_launch(void* const* d_in, const int* in_sizes, int n_in,
                              void* d_out, int out_size)
{
    const int*   xb      = (const int*)  d_in[0];
    const int*   targets = (const int*)  d_in[1];
    const float* Cemb    = (const float*)d_in[2];
    const float* Uw      = (const float*)d_in[3];
    const float* Ub      = (const float*)d_in[4];
    const float* Ww      = (const float*)d_in[5];
    const float* Vw      = (const float*)d_in[6];
    const float* Vb      = (const float*)d_in[7];
    float* out = (float*)d_out;

    k_uproj<<<dim3(16, 64), 256>>>(xb, Cemb, Uw, Ub);
    k_rnn_init<<<256, 256>>>();
    k_packW<<<dim3(64, 128), 512>>>(Ww);
    k_round_vw<<<64000, 256>>>(Vw);

    // recurrence: one kernel per step (kernel boundary = barrier; no spin)
    cudaFuncSetAttribute((const void*)k_step,
                         cudaFuncAttributeMaxDynamicSharedMemorySize, 114688);
    for (int t = 0; t < TT; ++t) {
        k_step<<<128, 256, 114688>>>(t);
    }

    // big vocab GEMM on tensor cores (tf32) with fused loss exp-partials
    cudaFuncSetAttribute((const void*)k_vgemm,
                         cudaFuncAttributeMaxDynamicSharedMemorySize, 3*VSTAGE*4);
    k_vgemm<<<8000, 256, 3*VSTAGE*4>>>(Vb, out);

    // loss finalize
    k_rowfinish<<<32, 256>>>(out, targets);
    k_loss<<<1, 256>>>(out, out_size);
}

// round 15
// speedup vs baseline: 1.3423x; 1.3423x over previous
#include <cuda_runtime.h>
#include <cuda_fp16.h>
#include <cstdint>
#include <math.h>

#define BB 32
#define TT 256
#define DD 512
#define HH 2048
#define VV 32000
#define BT (BB*TT)          // 8192

// ---------------- scratch (device globals; no allocation allowed) ------------
__device__ float g_ux[BT*HH];            // [T][B][H] input projection
__device__ __half g_hh[(size_t)BT*HH];   // h fp16, K-permuted in 32-blk (32MB)
__device__ float g_hT[2][HH*BB];         // transposed h double buffer [k][b]
__device__ float g_wP[(size_t)HH*HH];    // W packed: [blk][k][16 cols]
__device__ __half g_vh[(size_t)VV*HH];   // V_w fp16, K-permuted in 32-blk (128MB)
__device__ float g_rowloss[BT];

// ---------------- f32x2 packed helpers --------------------------------------
__device__ __forceinline__ unsigned long long pk2(float a, float b) {
    unsigned long long r;
    asm("mov.b64 %0, {%1, %2};" : "=l"(r) : "f"(a), "f"(b));
    return r;
}
__device__ __forceinline__ void fma2(unsigned long long& acc,
                                     unsigned long long a, unsigned long long b) {
    asm("fma.rn.f32x2 %0, %1, %2, %0;" : "+l"(acc) : "l"(a), "l"(b));
}
__device__ __forceinline__ void unpk2(unsigned long long v, float& lo, float& hi) {
    asm("mov.b64 {%0, %1}, %2;" : "=f"(lo), "=f"(hi) : "l"(v));
}

// ======================= Kernel A: ux = C[xb] @ U^T + b  (R12 version) =======
__global__ __launch_bounds__(256) void k_uproj(const int* __restrict__ xb,
                                               const float* __restrict__ Cemb,
                                               const float* __restrict__ Uw,
                                               const float* __restrict__ Ub)
{
    __shared__ float As[16][128];
    __shared__ float Bs[16][128];
    const int bn = blockIdx.x, bm = blockIdx.y;
    const int tid = threadIdx.x;
    const int tx = tid & 15, ty = tid >> 4;

    float acc[8][8];
    #pragma unroll
    for (int i = 0; i < 8; ++i)
        #pragma unroll
        for (int j = 0; j < 8; ++j) acc[i][j] = 0.f;

    for (int c = 0; c < DD/16; ++c) {
        const int k0 = c * 16;
        #pragma unroll
        for (int it = 0; it < 2; ++it) {
            int idx = tid + it*256;
            int r = idx & 127, q = idx >> 7;
            int tok = xb[bm*128 + r];
            float4 v = *(const float4*)&Cemb[(size_t)tok*DD + k0 + q*4];
            As[q*4+0][r] = v.x; As[q*4+1][r] = v.y;
            As[q*4+2][r] = v.z; As[q*4+3][r] = v.w;
        }
        #pragma unroll
        for (int it = 0; it < 2; ++it) {
            int idx = tid + it*256;
            int r = idx & 127, q = idx >> 7;
            float4 v = *(const float4*)&Uw[(size_t)(bn*128 + r)*DD + k0 + q*4];
            Bs[q*4+0][r] = v.x; Bs[q*4+1][r] = v.y;
            Bs[q*4+2][r] = v.z; Bs[q*4+3][r] = v.w;
        }
        __syncthreads();
        #pragma unroll
        for (int k = 0; k < 16; ++k) {
            float a[8], b[8];
            *(float4*)(a)   = *(float4*)&As[k][ty*8];
            *(float4*)(a+4) = *(float4*)&As[k][ty*8+4];
            *(float4*)(b)   = *(float4*)&Bs[k][tx*8];
            *(float4*)(b+4) = *(float4*)&Bs[k][tx*8+4];
            #pragma unroll
            for (int i = 0; i < 8; ++i)
                #pragma unroll
                for (int j = 0; j < 8; ++j) acc[i][j] += a[i]*b[j];
        }
        __syncthreads();
    }
    const int n0 = bn*128 + tx*8;
    float ub[8];
    #pragma unroll
    for (int j = 0; j < 8; ++j) ub[j] = Ub[n0+j];
    #pragma unroll
    for (int i = 0; i < 8; ++i) {
        int m = bm*128 + ty*8 + i;       // m = b*TT + t
        int t = m & 255, b = m >> 8;
        size_t dst = ((size_t)t*BB + b)*HH + n0;
        float4 o0 = {acc[i][0]+ub[0], acc[i][1]+ub[1], acc[i][2]+ub[2], acc[i][3]+ub[3]};
        float4 o1 = {acc[i][4]+ub[4], acc[i][5]+ub[5], acc[i][6]+ub[6], acc[i][7]+ub[7]};
        *(float4*)&g_ux[dst]     = o0;
        *(float4*)&g_ux[dst + 4] = o1;
    }
}

// ============ pack W for the recurrence: g_wP[blk][k][c16] = W[blk*16+c][k] ==
__global__ __launch_bounds__(512) void k_packW(const float* __restrict__ Ww)
{
    __shared__ float tile[32][17];
    const int bx = blockIdx.x;           // k-tile (0..63)
    const int by = blockIdx.y;           // col-block (0..127)
    const int tid = threadIdx.x;
    {
        int c = tid >> 5, kk = tid & 31;
        tile[kk][c] = Ww[(size_t)(by*16 + c)*HH + bx*32 + kk];
    }
    __syncthreads();
    {
        int kk = tid >> 4, c = tid & 15;
        g_wP[(size_t)by*(HH*16) + (size_t)(bx*32 + kk)*16 + c] = tile[kk][c];
    }
}

// ===== V_w -> fp16, K-permuted within 32-blocks (gather: coalesced stores) ===
// perm: pos(k) = 8*((k>>1)&3) + (k&1) + ((k&8)>>2) + ((k&16)>>2), within 32-blk.
// Thread builds output halves [8*tg .. 8*tg+7] of one 32-block from 4 float2s.
__global__ __launch_bounds__(256) void k_half_vw(const float* __restrict__ Vw)
{
    const size_t row = blockIdx.x;       // 32000
    const float* src = Vw + row*HH;
    __half* dst = g_vh + row*HH;
    int o = threadIdx.x;                 // 0..255 = HH/8 outputs
    int blk = o >> 2, tg = o & 3;
    int base = blk*32;
    float2 p0 = *(const float2*)&src[base + 2*tg];          // k 2tg,2tg+1
    float2 p1 = *(const float2*)&src[base + 2*tg + 8];      // k 2tg+8,+9
    float2 p2 = *(const float2*)&src[base + 16 + 2*tg];     // k 16+2tg,+1
    float2 p3 = *(const float2*)&src[base + 16 + 2*tg + 8]; // k 16+2tg+8,+9
    __half2 h0 = __floats2half2_rn(p0.x, p0.y);
    __half2 h1 = __floats2half2_rn(p1.x, p1.y);
    __half2 h2 = __floats2half2_rn(p2.x, p2.y);
    __half2 h3 = __floats2half2_rn(p3.x, p3.y);
    uint4 v;
    v.x = *(unsigned*)&h0; v.y = *(unsigned*)&h1;
    v.z = *(unsigned*)&h2; v.w = *(unsigned*)&h3;
    *(uint4*)&dst[base + 8*tg] = v;
}

// ============== prologue: h0 fill (graph-replay safe) ========================
__global__ __launch_bounds__(256) void k_rnn_init()
{
    int i = blockIdx.x*256 + threadIdx.x;
    g_hT[0][i] = 0.1f;
}

// ================= one Elman timestep: h_t = tanh(ux_t + W h_{t-1}) ==========
// (R12 version; only the h output for the V-GEMM changed: fp16 + 32-blk perm)
__global__ __launch_bounds__(256, 1) void k_step(int t)
{
    extern __shared__ float sm[];
    float* hs   = sm;            // 2 x [256 k][32 b] = 16384 floats (64 KB)
    float* ws   = sm + 16384;    // 2 x [256 k][16 c] =  8192 floats (32 KB)
    float* part = sm + 24576;    // [8][512]          =  4096 floats (16 KB)

    const int tid = threadIdx.x;
    const int c2 = tid & 7;
    const int rg = (tid >> 3) & 3;
    const int ks = tid >> 5;                 // warp index = k-slice
    const int cb = blockIdx.x * 16;

    const float4* hsrc = (const float4*)&g_hT[t & 1][0];   // 16384 float4
    const float4* wsrc = (const float4*)(g_wP + (size_t)blockIdx.x*(HH*16));

    auto stage = [&](int c, int s) {
        float* hd = hs + s*8192;
        #pragma unroll
        for (int i = 0; i < 8; ++i) {
            int idx = tid + i*256;
            unsigned d = (unsigned)__cvta_generic_to_shared(hd + idx*4);
            asm volatile("cp.async.cg.shared.global [%0], [%1], 16;\n"
                         :: "r"(d), "l"(hsrc + c*2048 + idx));
        }
        float* wd = ws + s*4096;
        #pragma unroll
        for (int i = 0; i < 4; ++i) {
            int idx = tid + i*256;
            unsigned d = (unsigned)__cvta_generic_to_shared(wd + idx*4);
            asm volatile("cp.async.cg.shared.global [%0], [%1], 16;\n"
                         :: "r"(d), "l"(wsrc + c*1024 + idx));
        }
        asm volatile("cp.async.commit_group;\n");
    };

    stage(0, 0);

    unsigned long long a00=0, a01=0, a02=0, a03=0;
    unsigned long long a10=0, a11=0, a12=0, a13=0;

    for (int ch = 0; ch < 8; ++ch) {
        if (ch < 7) {
            stage(ch + 1, (ch + 1) & 1);
            asm volatile("cp.async.wait_group 1;\n");
        } else {
            asm volatile("cp.async.wait_group 0;\n");
        }
        __syncthreads();

        unsigned hba = (unsigned)__cvta_generic_to_shared(
            hs + (ch & 1)*8192 + (ks*32)*32 + rg*8);
        unsigned wba = (unsigned)__cvta_generic_to_shared(
            ws + (ch & 1)*4096 + (ks*32)*16 + c2*2);

        #pragma unroll 8
        for (int kl = 0; kl < 32; ++kl) {
            float wx, wy;
            asm("ld.shared.v2.f32 {%0, %1}, [%2];" : "=f"(wx), "=f"(wy) : "r"(wba));
            wba += 64;
            unsigned long long w0 = pk2(wx, wx);
            unsigned long long w1 = pk2(wy, wy);
            unsigned long long h01, h23, h45, h67;
            asm("ld.shared.v2.u64 {%0,%1}, [%2];"
                : "=l"(h01), "=l"(h23) : "r"(hba));
            asm("ld.shared.v2.u64 {%0,%1}, [%2];"
                : "=l"(h45), "=l"(h67) : "r"(hba + 16));
            hba += 128;
            fma2(a00, h01, w0); fma2(a01, h23, w0);
            fma2(a02, h45, w0); fma2(a03, h67, w0);
            fma2(a10, h01, w1); fma2(a11, h23, w1);
            fma2(a12, h45, w1); fma2(a13, h67, w1);
        }
        __syncthreads();
    }

    {
        float lo, hi;
        float* p0 = &part[ks*512 + (c2*2 + 0)*32 + rg*8];
        float* p1 = &part[ks*512 + (c2*2 + 1)*32 + rg*8];
        unpk2(a00, lo, hi); p0[0] = lo; p0[1] = hi;
        unpk2(a01, lo, hi); p0[2] = lo; p0[3] = hi;
        unpk2(a02, lo, hi); p0[4] = lo; p0[5] = hi;
        unpk2(a03, lo, hi); p0[6] = lo; p0[7] = hi;
        unpk2(a10, lo, hi); p1[0] = lo; p1[1] = hi;
        unpk2(a11, lo, hi); p1[2] = lo; p1[3] = hi;
        unpk2(a12, lo, hi); p1[4] = lo; p1[5] = hi;
        unpk2(a13, lo, hi); p1[6] = lo; p1[7] = hi;
    }
    __syncthreads();

    #pragma unroll
    for (int u = 0; u < 2; ++u) {
        int o = tid*2 + u;
        int c = o >> 5, b = o & 31;
        float s = part[o] + part[512 + o] + part[1024 + o] + part[1536 + o]
                + part[2048 + o] + part[2560 + o] + part[3072 + o] + part[3584 + o];
        s += g_ux[((size_t)t*BB + b)*HH + cb + c];
        float h = tanhf(s);
        g_hT[(t+1) & 1][(size_t)(cb + c)*BB + b] = h;
        // fp16 h, K-permuted within the surrounding 32-block
        int kk = (cb & 16) + c;                    // position within 32-block
        int pos = ((kk >> 1) & 3)*8 + (kk & 1) + ((kk & 8) >> 2) + ((kk & 16) >> 2);
        size_t base32 = (size_t)(cb & ~31);
        g_hh[((size_t)b*TT + t)*HH + base32 + pos] = __float2half(h);
    }
}

// ============ Kernel C: logits = h @ V_w^T + V_b  (fp16 m16n8k16 MMA) ========
// M=8192 N=32000 K=2048. Block 128x256, BK=32 halves, 8 warps (2x4), warp 64x64.
// K perm in 32-blocks makes each thread's full chunk fragment ONE LDS.128/row.
#define VSTAGE 12288    // halves per stage: A 128x32 (4096) + B 256x32 (8192)
__global__ __launch_bounds__(256, 1) void k_vgemm(const float* __restrict__ Vb,
                                                  float* __restrict__ out)
{
    extern __shared__ __half smh[];

    const int bid = blockIdx.x;                 // 8000 = 8 grp x (8 bm x 125 bn)
    const int grp = bid / 1000;
    const int rem = bid % 1000;
    const int bm  = grp*8 + (rem & 7);          // 0..63
    const int bn  = rem >> 3;                   // 0..124

    const int tid = threadIdx.x;
    const int lane = tid & 31, wid = tid >> 5;
    const int wm = (wid >> 2) * 64, wn = (wid & 3) * 64;
    const int gr = lane >> 2, tg = lane & 3;

    const __half* Ag = g_hh + (size_t)(bm*128)*HH;
    const __half* Bg = g_vh + (size_t)(bn*256)*HH;

    float acc[4][8][4];
    #pragma unroll
    for (int m = 0; m < 4; ++m)
        #pragma unroll
        for (int n = 0; n < 8; ++n)
            #pragma unroll
            for (int q = 0; q < 4; ++q) acc[m][n][q] = 0.f;

    auto stage_load = [&](int c, int s) {
        __half* As = smh + s*VSTAGE;
        __half* Bs = As + 4096;
        #pragma unroll
        for (int i = 0; i < 2; ++i) {             // A: 512 x 16B
            int o = tid + i*256;
            int row = o >> 2, seg = o & 3;
            unsigned d = (unsigned)__cvta_generic_to_shared(As + (size_t)o*8);
            const __half* src = Ag + (size_t)row*HH + c*32 + seg*8;
            asm volatile("cp.async.cg.shared.global [%0], [%1], 16;\n"
                         :: "r"(d), "l"(src));
        }
        #pragma unroll
        for (int i = 0; i < 4; ++i) {             // B: 1024 x 16B
            int o = tid + i*256;
            int row = o >> 2, seg = o & 3;
            unsigned d = (unsigned)__cvta_generic_to_shared(Bs + (size_t)o*8);
            const __half* src = Bg + (size_t)row*HH + c*32 + seg*8;
            asm volatile("cp.async.cg.shared.global [%0], [%1], 16;\n"
                         :: "r"(d), "l"(src));
        }
        asm volatile("cp.async.commit_group;\n");
    };

    stage_load(0, 0);
    stage_load(1, 1);

    int sc = 0, sl = 2;
    const int NCH = HH/32;                        // 64 chunks
    for (int c = 0; c < NCH; ++c) {
        if (c < NCH-1) asm volatile("cp.async.wait_group 1;\n");
        else           asm volatile("cp.async.wait_group 0;\n");
        __syncthreads();
        if (c + 2 < NCH) {
            stage_load(c + 2, sl);
            sl = (sl == 2) ? 0 : sl + 1;
        }

        const __half* As = smh + sc*VSTAGE;
        const __half* Bs = As + 4096;

        uint4 uA[4], uB[4], uN[8];
        #pragma unroll
        for (int mt = 0; mt < 4; ++mt) {
            uA[mt] = *(const uint4*)&As[(wm + mt*16 + gr)*32 + tg*8];
            uB[mt] = *(const uint4*)&As[(wm + mt*16 + 8 + gr)*32 + tg*8];
        }
        #pragma unroll
        for (int nt = 0; nt < 8; ++nt)
            uN[nt] = *(const uint4*)&Bs[(wn + nt*8 + gr)*32 + tg*8];

        #pragma unroll
        for (int mt = 0; mt < 4; ++mt)
            #pragma unroll
            for (int nt = 0; nt < 8; ++nt) {
                asm volatile(
                    "mma.sync.aligned.m16n8k16.row.col.f32.f16.f16.f32 "
                    "{%0,%1,%2,%3},{%4,%5,%6,%7},{%8,%9},{%0,%1,%2,%3};\n"
                    : "+f"(acc[mt][nt][0]), "+f"(acc[mt][nt][1]),
                      "+f"(acc[mt][nt][2]), "+f"(acc[mt][nt][3])
                    : "r"(uA[mt].x), "r"(uB[mt].x), "r"(uA[mt].y), "r"(uB[mt].y),
                      "r"(uN[nt].x), "r"(uN[nt].y));
                asm volatile(
                    "mma.sync.aligned.m16n8k16.row.col.f32.f16.f16.f32 "
                    "{%0,%1,%2,%3},{%4,%5,%6,%7},{%8,%9},{%0,%1,%2,%3};\n"
                    : "+f"(acc[mt][nt][0]), "+f"(acc[mt][nt][1]),
                      "+f"(acc[mt][nt][2]), "+f"(acc[mt][nt][3])
                    : "r"(uA[mt].z), "r"(uB[mt].z), "r"(uA[mt].w), "r"(uB[mt].w),
                      "r"(uN[nt].z), "r"(uN[nt].w));
            }
        sc = (sc == 2) ? 0 : sc + 1;
    }

    // epilogue: +bias, store fp32 logits (R12 style, no fusion)
    #pragma unroll
    for (int mt = 0; mt < 4; ++mt) {
        size_t r0 = (size_t)(bm*128 + wm + mt*16 + gr);
        #pragma unroll
        for (int nt = 0; nt < 8; ++nt) {
            int col = bn*256 + wn + nt*8 + tg*2;
            float b0 = Vb[col], b1 = Vb[col+1];
            float2 v0 = {acc[mt][nt][0] + b0, acc[mt][nt][1] + b1};
            float2 v1 = {acc[mt][nt][2] + b0, acc[mt][nt][3] + b1};
            *(float2*)&out[r0*VV + col]       = v0;
            *(float2*)&out[(r0+8)*VV + col]   = v1;
        }
    }
}

// ====== Kernel D1: log-softmax loss via f16x2 ex2 (no max pass needed) =======
__global__ __launch_bounds__(256) void k_rowloss(const float* __restrict__ logits,
                                                 const int* __restrict__ targets)
{
    __shared__ float ssm[256];
    const int r = blockIdx.x;
    const int tid = threadIdx.x;
    const float4* row4 = (const float4*)(logits + (size_t)r*VV);
    const float C = 1.4426950408889634f;   // log2(e)

    float s0 = 0.f, s1 = 0.f;
    for (int i = tid; i < VV/4; i += 256) {
        float4 v = row4[i];
        float y0 = fmaf(v.x, C, -8.f);
        float y1 = fmaf(v.y, C, -8.f);
        float y2 = fmaf(v.z, C, -8.f);
        float y3 = fmaf(v.w, C, -8.f);
        uint32_t h01, h23, e01, e23;
        asm("cvt.rn.f16x2.f32 %0, %1, %2;" : "=r"(h01) : "f"(y1), "f"(y0));
        asm("cvt.rn.f16x2.f32 %0, %1, %2;" : "=r"(h23) : "f"(y3), "f"(y2));
        asm("ex2.approx.f16x2 %0, %1;" : "=r"(e01) : "r"(h01));
        asm("ex2.approx.f16x2 %0, %1;" : "=r"(e23) : "r"(h23));
        float a, b, c2, d;
        asm("{.reg .f16 l,h; mov.b32 {l,h}, %2; cvt.f32.f16 %0, l; cvt.f32.f16 %1, h;}"
            : "=f"(a), "=f"(b) : "r"(e01));
        asm("{.reg .f16 l,h; mov.b32 {l,h}, %2; cvt.f32.f16 %0, l; cvt.f32.f16 %1, h;}"
            : "=f"(c2), "=f"(d) : "r"(e23));
        s0 += a + b;
        s1 += c2 + d;
    }
    ssm[tid] = s0 + s1;
    __syncthreads();
    for (int st = 128; st > 0; st >>= 1) {
        if (tid < st) ssm[tid] += ssm[tid + st];
        __syncthreads();
    }
    if (tid == 0) {
        float lse = (__log2f(ssm[0]) + 8.f) * 0.6931471805599453f;
        g_rowloss[r] = lse - logits[(size_t)r*VV + targets[r]];
    }
}

// ================= Kernel D2: mean of row losses -> d_out[last] ==============
__global__ __launch_bounds__(256) void k_loss(float* __restrict__ out, int out_size)
{
    __shared__ float red[256];
    const int tid = threadIdx.x;
    float s = 0.f;
    for (int i = tid; i < BT; i += 256) s += g_rowloss[i];
    red[tid] = s; __syncthreads();
    for (int st = 128; st > 0; st >>= 1) {
        if (tid < st) red[tid] += red[tid+st];
        __syncthreads();
    }
    if (tid == 0) out[(size_t)out_size - 1] = red[0] / (float)BT;
}

// ============================== launch =======================================
extern "C" void kernel_launch(void* const* d_in, const int* in_sizes, int n_in,
                              void* d_out, int out_size)
{
    const int*   xb      = (const int*)  d_in[0];
    const int*   targets = (const int*)  d_in[1];
    const float* Cemb    = (const float*)d_in[2];
    const float* Uw      = (const float*)d_in[3];
    const float* Ub      = (const float*)d_in[4];
    const float* Ww      = (const float*)d_in[5];
    const float* Vw      = (const float*)d_in[6];
    const float* Vb      = (const float*)d_in[7];
    float* out = (float*)d_out;

    // order: ncu skips 5 launches -> capture lands on k_step t=1 (steady state)
    k_uproj<<<dim3(16, 64), 256>>>(xb, Cemb, Uw, Ub);       // 1
    k_rnn_init<<<256, 256>>>();                              // 2
    k_packW<<<dim3(64, 128), 512>>>(Ww);                     // 3
    k_half_vw<<<VV, 256>>>(Vw);                              // 4

    // recurrence: one kernel per step (kernel boundary = barrier; no spin)
    cudaFuncSetAttribute((const void*)k_step,
                         cudaFuncAttributeMaxDynamicSharedMemorySize, 114688);
    for (int t = 0; t < TT; ++t) {
        k_step<<<128, 256, 114688>>>(t);                     // 5 .. 260
    }

    // big vocab GEMM on tensor cores (fp16 m16n8k16, fp32 accum, 3-stage)
    cudaFuncSetAttribute((const void*)k_vgemm,
                         cudaFuncAttributeMaxDynamicSharedMemorySize, 3*VSTAGE*2);
    k_vgemm<<<8000, 256, 3*VSTAGE*2>>>(Vb, out);

    // loss
    k_rowloss<<<BT, 256>>>(out, targets);
    k_loss<<<1, 256>>>(out, out_size);
}

// round 16
// speedup vs baseline: 1.5209x; 1.1330x over previous
#include <cuda_runtime.h>
#include <cstdint>
#include <math.h>

#define BB 32
#define TT 256
#define DD 512
#define HH 2048
#define VV 32000
#define BT (BB*TT)          // 8192

// ---------------- scratch (device globals; no allocation allowed) ------------
__device__ float g_ux[BT*HH];            // [T][B][H] input projection
__device__ float g_hr[BT*HH];            // [B,T,H] tf32 h, K-permuted in 16-blk
__device__ float g_hT[2][HH*BB];         // transposed h double buffer [k][b]
__device__ float g_wP[(size_t)HH*HH];    // W packed: [blk][k][16 cols]
__device__ float g_vw[(size_t)VV*HH];    // tf32 V_w, K-permuted in 16-blk
__device__ float g_rowloss[BT];

// ---------------- f32x2 packed helpers --------------------------------------
__device__ __forceinline__ unsigned long long pk2(float a, float b) {
    unsigned long long r;
    asm("mov.b64 %0, {%1, %2};" : "=l"(r) : "f"(a), "f"(b));
    return r;
}
__device__ __forceinline__ void fma2(unsigned long long& acc,
                                     unsigned long long a, unsigned long long b) {
    asm("fma.rn.f32x2 %0, %1, %2, %0;" : "+l"(acc) : "l"(a), "l"(b));
}
__device__ __forceinline__ void unpk2(unsigned long long v, float& lo, float& hi) {
    asm("mov.b64 {%0, %1}, %2;" : "=f"(lo), "=f"(hi) : "l"(v));
}

// ======================= Kernel A: ux = C[xb] @ U^T + b ======================
__global__ __launch_bounds__(256) void k_uproj(const int* __restrict__ xb,
                                               const float* __restrict__ Cemb,
                                               const float* __restrict__ Uw,
                                               const float* __restrict__ Ub)
{
    __shared__ float As[16][128];
    __shared__ float Bs[16][128];
    const int bn = blockIdx.x, bm = blockIdx.y;
    const int tid = threadIdx.x;
    const int tx = tid & 15, ty = tid >> 4;

    float acc[8][8];
    #pragma unroll
    for (int i = 0; i < 8; ++i)
        #pragma unroll
        for (int j = 0; j < 8; ++j) acc[i][j] = 0.f;

    for (int c = 0; c < DD/16; ++c) {
        const int k0 = c * 16;
        #pragma unroll
        for (int it = 0; it < 2; ++it) {
            int idx = tid + it*256;
            int r = idx & 127, q = idx >> 7;
            int tok = xb[bm*128 + r];
            float4 v = *(const float4*)&Cemb[(size_t)tok*DD + k0 + q*4];
            As[q*4+0][r] = v.x; As[q*4+1][r] = v.y;
            As[q*4+2][r] = v.z; As[q*4+3][r] = v.w;
        }
        #pragma unroll
        for (int it = 0; it < 2; ++it) {
            int idx = tid + it*256;
            int r = idx & 127, q = idx >> 7;
            float4 v = *(const float4*)&Uw[(size_t)(bn*128 + r)*DD + k0 + q*4];
            Bs[q*4+0][r] = v.x; Bs[q*4+1][r] = v.y;
            Bs[q*4+2][r] = v.z; Bs[q*4+3][r] = v.w;
        }
        __syncthreads();
        #pragma unroll
        for (int k = 0; k < 16; ++k) {
            float a[8], b[8];
            *(float4*)(a)   = *(float4*)&As[k][ty*8];
            *(float4*)(a+4) = *(float4*)&As[k][ty*8+4];
            *(float4*)(b)   = *(float4*)&Bs[k][tx*8];
            *(float4*)(b+4) = *(float4*)&Bs[k][tx*8+4];
            #pragma unroll
            for (int i = 0; i < 8; ++i)
                #pragma unroll
                for (int j = 0; j < 8; ++j) acc[i][j] += a[i]*b[j];
        }
        __syncthreads();
    }
    const int n0 = bn*128 + tx*8;
    float ub[8];
    #pragma unroll
    for (int j = 0; j < 8; ++j) ub[j] = Ub[n0+j];
    #pragma unroll
    for (int i = 0; i < 8; ++i) {
        int m = bm*128 + ty*8 + i;       // m = b*TT + t
        int t = m & 255, b = m >> 8;
        size_t dst = ((size_t)t*BB + b)*HH + n0;
        float4 o0 = {acc[i][0]+ub[0], acc[i][1]+ub[1], acc[i][2]+ub[2], acc[i][3]+ub[3]};
        float4 o1 = {acc[i][4]+ub[4], acc[i][5]+ub[5], acc[i][6]+ub[6], acc[i][7]+ub[7]};
        *(float4*)&g_ux[dst]     = o0;
        *(float4*)&g_ux[dst + 4] = o1;
    }
}

// ============ pack W for the recurrence: g_wP[blk][k][c16] = W[blk*16+c][k] ==
__global__ __launch_bounds__(512) void k_packW(const float* __restrict__ Ww)
{
    __shared__ float tile[32][17];
    const int bx = blockIdx.x;           // k-tile (0..63)
    const int by = blockIdx.y;           // col-block (0..127)
    const int tid = threadIdx.x;
    {
        int c = tid >> 5, kk = tid & 31;
        tile[kk][c] = Ww[(size_t)(by*16 + c)*HH + bx*32 + kk];
    }
    __syncthreads();
    {
        int kk = tid >> 4, c = tid & 15;
        g_wP[(size_t)by*(HH*16) + (size_t)(bx*32 + kk)*16 + c] = tile[kk][c];
    }
}

// ===== pre-round V_w to tf32, store K-permuted within 16-blocks ==============
__global__ __launch_bounds__(256) void k_round_vw(const float* __restrict__ Vw)
{
    size_t i = ((size_t)blockIdx.x*256 + threadIdx.x) * 4;
    float4 v = *(const float4*)&Vw[i];
    float4 o;
    asm("cvt.rna.tf32.f32 %0, %1;" : "=f"(o.x) : "f"(v.x));
    asm("cvt.rna.tf32.f32 %0, %1;" : "=f"(o.y) : "f"(v.y));
    asm("cvt.rna.tf32.f32 %0, %1;" : "=f"(o.z) : "f"(v.z));
    asm("cvt.rna.tf32.f32 %0, %1;" : "=f"(o.w) : "f"(v.w));
    size_t base16 = i & ~(size_t)15;
    size_t q = (i >> 2) & 3;
    g_vw[base16 + q + 0]  = o.x;
    g_vw[base16 + q + 4]  = o.y;
    g_vw[base16 + q + 8]  = o.z;
    g_vw[base16 + q + 12] = o.w;
}

// ============== prologue: h0 fill (graph-replay safe) ========================
__global__ __launch_bounds__(256) void k_rnn_init()
{
    int i = blockIdx.x*256 + threadIdx.x;
    g_hT[0][i] = 0.1f;
}

// ================= one Elman timestep: h_t = tanh(ux_t + W h_{t-1}) ==========
__global__ __launch_bounds__(256, 1) void k_step(int t)
{
    extern __shared__ float sm[];
    float* hs   = sm;            // 2 x [256 k][32 b] = 16384 floats (64 KB)
    float* ws   = sm + 16384;    // 2 x [256 k][16 c] =  8192 floats (32 KB)
    float* part = sm + 24576;    // [8][512]          =  4096 floats (16 KB)

    const int tid = threadIdx.x;
    const int c2 = tid & 7;
    const int rg = (tid >> 3) & 3;
    const int ks = tid >> 5;                 // warp index = k-slice
    const int cb = blockIdx.x * 16;

    const float4* hsrc = (const float4*)&g_hT[t & 1][0];   // 16384 float4
    const float4* wsrc = (const float4*)(g_wP + (size_t)blockIdx.x*(HH*16));

    auto stage = [&](int c, int s) {
        float* hd = hs + s*8192;
        #pragma unroll
        for (int i = 0; i < 8; ++i) {
            int idx = tid + i*256;
            unsigned d = (unsigned)__cvta_generic_to_shared(hd + idx*4);
            asm volatile("cp.async.cg.shared.global [%0], [%1], 16;\n"
                         :: "r"(d), "l"(hsrc + c*2048 + idx));
        }
        float* wd = ws + s*4096;
        #pragma unroll
        for (int i = 0; i < 4; ++i) {
            int idx = tid + i*256;
            unsigned d = (unsigned)__cvta_generic_to_shared(wd + idx*4);
            asm volatile("cp.async.cg.shared.global [%0], [%1], 16;\n"
                         :: "r"(d), "l"(wsrc + c*1024 + idx));
        }
        asm volatile("cp.async.commit_group;\n");
    };

    stage(0, 0);

    unsigned long long a00=0, a01=0, a02=0, a03=0;
    unsigned long long a10=0, a11=0, a12=0, a13=0;

    for (int ch = 0; ch < 8; ++ch) {
        if (ch < 7) {
            stage(ch + 1, (ch + 1) & 1);
            asm volatile("cp.async.wait_group 1;\n");
        } else {
            asm volatile("cp.async.wait_group 0;\n");
        }
        __syncthreads();

        unsigned hba = (unsigned)__cvta_generic_to_shared(
            hs + (ch & 1)*8192 + (ks*32)*32 + rg*8);
        unsigned wba = (unsigned)__cvta_generic_to_shared(
            ws + (ch & 1)*4096 + (ks*32)*16 + c2*2);

        #pragma unroll 8
        for (int kl = 0; kl < 32; ++kl) {
            float wx, wy;
            asm("ld.shared.v2.f32 {%0, %1}, [%2];" : "=f"(wx), "=f"(wy) : "r"(wba));
            wba += 64;
            unsigned long long w0 = pk2(wx, wx);
            unsigned long long w1 = pk2(wy, wy);
            unsigned long long h01, h23, h45, h67;
            asm("ld.shared.v2.u64 {%0,%1}, [%2];"
                : "=l"(h01), "=l"(h23) : "r"(hba));
            asm("ld.shared.v2.u64 {%0,%1}, [%2];"
                : "=l"(h45), "=l"(h67) : "r"(hba + 16));
            hba += 128;
            fma2(a00, h01, w0); fma2(a01, h23, w0);
            fma2(a02, h45, w0); fma2(a03, h67, w0);
            fma2(a10, h01, w1); fma2(a11, h23, w1);
            fma2(a12, h45, w1); fma2(a13, h67, w1);
        }
        __syncthreads();
    }

    {
        float lo, hi;
        float* p0 = &part[ks*512 + (c2*2 + 0)*32 + rg*8];
        float* p1 = &part[ks*512 + (c2*2 + 1)*32 + rg*8];
        unpk2(a00, lo, hi); p0[0] = lo; p0[1] = hi;
        unpk2(a01, lo, hi); p0[2] = lo; p0[3] = hi;
        unpk2(a02, lo, hi); p0[4] = lo; p0[5] = hi;
        unpk2(a03, lo, hi); p0[6] = lo; p0[7] = hi;
        unpk2(a10, lo, hi); p1[0] = lo; p1[1] = hi;
        unpk2(a11, lo, hi); p1[2] = lo; p1[3] = hi;
        unpk2(a12, lo, hi); p1[4] = lo; p1[5] = hi;
        unpk2(a13, lo, hi); p1[6] = lo; p1[7] = hi;
    }
    __syncthreads();

    #pragma unroll
    for (int u = 0; u < 2; ++u) {
        int o = tid*2 + u;
        int c = o >> 5, b = o & 31;
        float s = part[o] + part[512 + o] + part[1024 + o] + part[1536 + o]
                + part[2048 + o] + part[2560 + o] + part[3072 + o] + part[3584 + o];
        s += g_ux[((size_t)t*BB + b)*HH + cb + c];
        float h = tanhf(s);
        g_hT[(t+1) & 1][(size_t)(cb + c)*BB + b] = h;
        float hr; asm("cvt.rna.tf32.f32 %0, %1;" : "=f"(hr) : "f"(h));
        int permc = ((c & 3) << 2) | (c >> 2);
        g_hr[((size_t)b*TT + t)*HH + cb + permc] = hr;
    }
}

// ================= Kernel C: logits = h @ V_w^T + V_b  (tf32 MMA) ============
#define VSTAGE 12288    // floats per stage: A 128x32 (4096) + B 256x32 (8192)
__global__ __launch_bounds__(256, 1) void k_vgemm(const float* __restrict__ Vb,
                                                  float* __restrict__ out)
{
    extern __shared__ float smv[];

    const int bid = blockIdx.x;                 // 8000 = 8 grp x (8 bm x 125 bn)
    const int grp = bid / 1000;
    const int rem = bid % 1000;
    const int bm  = grp*8 + (rem & 7);          // 0..63
    const int bn  = rem >> 3;                   // 0..124

    const int tid = threadIdx.x;
    const int lane = tid & 31, wid = tid >> 5;
    const int wm = (wid >> 2) * 64, wn = (wid & 3) * 64;
    const int gr = lane >> 2, tg = lane & 3;

    const float* Ag = g_hr + (size_t)(bm*128)*HH;
    const float* Bg = g_vw + (size_t)(bn*256)*HH;

    float acc[4][8][4];
    #pragma unroll
    for (int m = 0; m < 4; ++m)
        #pragma unroll
        for (int n = 0; n < 8; ++n)
            #pragma unroll
            for (int q = 0; q < 4; ++q) acc[m][n][q] = 0.f;

    auto stage_load = [&](int c, int s) {
        float* As = smv + s*VSTAGE;
        float* Bs = As + 4096;
        #pragma unroll
        for (int i = 0; i < 4; ++i) {             // A: 1024 x 16B
            int o = tid + i*256;
            int kg = o >> 9, row = (o >> 2) & 127, q = o & 3;
            unsigned d = (unsigned)__cvta_generic_to_shared(As + o*4);
            const float* src = Ag + (size_t)row*HH + c*32 + kg*16 + q*4;
            asm volatile("cp.async.cg.shared.global [%0], [%1], 16;\n"
                         :: "r"(d), "l"(src));
        }
        #pragma unroll
        for (int i = 0; i < 8; ++i) {             // B: 2048 x 16B
            int o = tid + i*256;
            int kg = o >> 10, row = (o >> 2) & 255, q = o & 3;
            unsigned d = (unsigned)__cvta_generic_to_shared(Bs + o*4);
            const float* src = Bg + (size_t)row*HH + c*32 + kg*16 + q*4;
            asm volatile("cp.async.cg.shared.global [%0], [%1], 16;\n"
                         :: "r"(d), "l"(src));
        }
        asm volatile("cp.async.commit_group;\n");
    };

    stage_load(0, 0);
    stage_load(1, 1);

    int sc = 0, sl = 2;
    const int NCH = HH/32;                        // 64 chunks
    for (int c = 0; c < NCH; ++c) {
        if (c < NCH-1) asm volatile("cp.async.wait_group 1;\n");
        else           asm volatile("cp.async.wait_group 0;\n");
        __syncthreads();
        if (c + 2 < NCH) {
            stage_load(c + 2, sl);
            sl = (sl == 2) ? 0 : sl + 1;
        }

        const float* As = smv + sc*VSTAGE;
        const float* Bs = As + 4096;
        #pragma unroll
        for (int kg = 0; kg < 2; ++kg) {
            float4 af[4][2]; float4 bf[8];
            #pragma unroll
            for (int mt = 0; mt < 4; ++mt) {
                af[mt][0] = *(const float4*)&As[(kg*128 + wm + mt*16 + gr)*16 + tg*4];
                af[mt][1] = *(const float4*)&As[(kg*128 + wm + mt*16 + 8 + gr)*16 + tg*4];
            }
            #pragma unroll
            for (int nt = 0; nt < 8; ++nt)
                bf[nt] = *(const float4*)&Bs[(kg*256 + wn + nt*8 + gr)*16 + tg*4];

            #pragma unroll
            for (int mt = 0; mt < 4; ++mt)
                #pragma unroll
                for (int nt = 0; nt < 8; ++nt) {
                    asm volatile(
                        "mma.sync.aligned.m16n8k8.row.col.f32.tf32.tf32.f32 "
                        "{%0,%1,%2,%3},{%4,%5,%6,%7},{%8,%9},{%0,%1,%2,%3};\n"
                        : "+f"(acc[mt][nt][0]), "+f"(acc[mt][nt][1]),
                          "+f"(acc[mt][nt][2]), "+f"(acc[mt][nt][3])
                        : "r"(__float_as_uint(af[mt][0].x)), "r"(__float_as_uint(af[mt][1].x)),
                          "r"(__float_as_uint(af[mt][0].y)), "r"(__float_as_uint(af[mt][1].y)),
                          "r"(__float_as_uint(bf[nt].x)),    "r"(__float_as_uint(bf[nt].y)));
                    asm volatile(
                        "mma.sync.aligned.m16n8k8.row.col.f32.tf32.tf32.f32 "
                        "{%0,%1,%2,%3},{%4,%5,%6,%7},{%8,%9},{%0,%1,%2,%3};\n"
                        : "+f"(acc[mt][nt][0]), "+f"(acc[mt][nt][1]),
                          "+f"(acc[mt][nt][2]), "+f"(acc[mt][nt][3])
                        : "r"(__float_as_uint(af[mt][0].z)), "r"(__float_as_uint(af[mt][1].z)),
                          "r"(__float_as_uint(af[mt][0].w)), "r"(__float_as_uint(af[mt][1].w)),
                          "r"(__float_as_uint(bf[nt].z)),    "r"(__float_as_uint(bf[nt].w)));
                }
        }
        sc = (sc == 2) ? 0 : sc + 1;
    }

    // epilogue: +bias, store fp32 logits
    #pragma unroll
    for (int mt = 0; mt < 4; ++mt) {
        size_t r0 = (size_t)(bm*128 + wm + mt*16 + gr);
        #pragma unroll
        for (int nt = 0; nt < 8; ++nt) {
            int col = bn*256 + wn + nt*8 + tg*2;
            float b0 = Vb[col], b1 = Vb[col+1];
            float2 v0 = {acc[mt][nt][0] + b0, acc[mt][nt][1] + b1};
            float2 v1 = {acc[mt][nt][2] + b0, acc[mt][nt][3] + b1};
            *(float2*)&out[r0*VV + col]       = v0;
            *(float2*)&out[(r0+8)*VV + col]   = v1;
        }
    }
}

// ====== Kernel D1: log-softmax loss via f16x2 ex2 (no max pass needed) =======
__global__ __launch_bounds__(256) void k_rowloss(const float* __restrict__ logits,
                                                 const int* __restrict__ targets)
{
    __shared__ float ssm[256];
    const int r = blockIdx.x;
    const int tid = threadIdx.x;
    const float4* row4 = (const float4*)(logits + (size_t)r*VV);
    const float C = 1.4426950408889634f;   // log2(e)

    float s0 = 0.f, s1 = 0.f;
    for (int i = tid; i < VV/4; i += 256) {
        float4 v = row4[i];
        float y0 = fmaf(v.x, C, -8.f);
        float y1 = fmaf(v.y, C, -8.f);
        float y2 = fmaf(v.z, C, -8.f);
        float y3 = fmaf(v.w, C, -8.f);
        uint32_t h01, h23, e01, e23;
        asm("cvt.rn.f16x2.f32 %0, %1, %2;" : "=r"(h01) : "f"(y1), "f"(y0));
        asm("cvt.rn.f16x2.f32 %0, %1, %2;" : "=r"(h23) : "f"(y3), "f"(y2));
        asm("ex2.approx.f16x2 %0, %1;" : "=r"(e01) : "r"(h01));
        asm("ex2.approx.f16x2 %0, %1;" : "=r"(e23) : "r"(h23));
        float a, b, c2, d;
        asm("{.reg .f16 l,h; mov.b32 {l,h}, %2; cvt.f32.f16 %0, l; cvt.f32.f16 %1, h;}"
            : "=f"(a), "=f"(b) : "r"(e01));
        asm("{.reg .f16 l,h; mov.b32 {l,h}, %2; cvt.f32.f16 %0, l; cvt.f32.f16 %1, h;}"
            : "=f"(c2), "=f"(d) : "r"(e23));
        s0 += a + b;
        s1 += c2 + d;
    }
    ssm[tid] = s0 + s1;
    __syncthreads();
    for (int st = 128; st > 0; st >>= 1) {
        if (tid < st) ssm[tid] += ssm[tid + st];
        __syncthreads();
    }
    if (tid == 0) {
        float lse = (__log2f(ssm[0]) + 8.f) * 0.6931471805599453f;
        g_rowloss[r] = lse - logits[(size_t)r*VV + targets[r]];
    }
}

// ================= Kernel D2: mean of row losses -> d_out[last] ==============
__global__ __launch_bounds__(256) void k_loss(float* __restrict__ out, int out_size)
{
    __shared__ float red[256];
    const int tid = threadIdx.x;
    float s = 0.f;
    for (int i = tid; i < BT; i += 256) s += g_rowloss[i];
    red[tid] = s; __syncthreads();
    for (int st = 128; st > 0; st >>= 1) {
        if (tid < st) red[tid] += red[tid+st];
        __syncthreads();
    }
    if (tid == 0) out[(size_t)out_size - 1] = red[0] / (float)BT;
}

// ============================== launch =======================================
extern "C" void kernel_launch(void* const* d_in, const int* in_sizes, int n_in,
                              void* d_out, int out_size)
{
    const int*   xb      = (const int*)  d_in[0];
    const int*   targets = (const int*)  d_in[1];
    const float* Cemb    = (const float*)d_in[2];
    const float* Uw      = (const float*)d_in[3];
    const float* Ub      = (const float*)d_in[4];
    const float* Ww      = (const float*)d_in[5];
    const float* Vw      = (const float*)d_in[6];
    const float* Vb      = (const float*)d_in[7];
    float* out = (float*)d_out;

    k_uproj<<<dim3(16, 64), 256>>>(xb, Cemb, Uw, Ub);       // 1
    k_rnn_init<<<256, 256>>>();                              // 2
    k_packW<<<dim3(64, 128), 512>>>(Ww);                     // 3
    k_round_vw<<<64000, 256>>>(Vw);                          // 4

    cudaFuncSetAttribute((const void*)k_step,
                         cudaFuncAttributeMaxDynamicSharedMemorySize, 114688);
    cudaFuncSetAttribute((const void*)k_vgemm,
                         cudaFuncAttributeMaxDynamicSharedMemorySize, 3*VSTAGE*4);

    k_step<<<128, 256, 114688>>>(0);                         // 5

    // PROBE (6th launch = ncu capture slot): 8-block vgemm on stale-but-
    // deterministic g_hr. Its output rows/cols are fully overwritten by the
    // real vgemm below, so correctness is unaffected. Cost ~60us; buys the
    // first real profile of the dominant kernel.
    k_vgemm<<<8, 256, 3*VSTAGE*4>>>(Vb, out);                // 6  <-- ncu

    // recurrence: one kernel per step (kernel boundary = barrier; no spin)
    for (int t = 1; t < TT; ++t) {
        k_step<<<128, 256, 114688>>>(t);
    }

    // big vocab GEMM on tensor cores (tf32, vectorized frag loads, 3-stage)
    k_vgemm<<<8000, 256, 3*VSTAGE*4>>>(Vb, out);

    // loss
    k_rowloss<<<BT, 256>>>(out, targets);
    k_loss<<<1, 256>>>(out, out_size);
}